// round 10
// baseline (speedup 1.0000x reference)
#include <cuda_runtime.h>
#include <cuda_fp16.h>
#include <cstdint>

// GAT layer, N=8192, Fin=128, Fout=64.
// inputs: x [N,128] f32, adj [N,N] f32 (0/1), W [128,64] f32, a [128,1] f32
// output: [N,64] f32

#define N      8192
#define FOUT   64
#define TI     128
#define TJ     32
#define JSPLIT 16
#define JRANGE (N / JSPLIT)     // 512
#define NT     (JRANGE / TJ)    // 16

#define ADJ_STR 40                        // floats per adj smem row (160 B, conflict-free)
#define WH_STR  72                        // halves per Wh smem row (144 B)
#define STAGE_ADJ_B (TI * ADJ_STR * 4)    // 20480
#define STAGE_WH_B  (TJ * WH_STR * 2)     // 4608
#define STAGE_B     (STAGE_ADJ_B + STAGE_WH_B)   // 25088
#define NSTAGE 3
#define SMEMB_BYTES (NSTAGE * STAGE_B)    // 75264

// ---------------- device scratch ----------------
__device__ float2 g_E1P[N];                  // (e^Wh1, e^{0.2 Wh1}) fp32
__device__ __half g_E2XH[N];                 // fp16 e^Wh2
__device__ __half g_E2YH[N];                 // fp16 e^{0.2 Wh2}
__device__ __half g_Wh_h[N * FOUT];          // Wh [j][f] fp16
__device__ float  g_acc[JSPLIT][N * FOUT];   // partial numerators [js][i][f]
__device__ float  g_den[JSPLIT][N];          // partial denominators

// ---------------- helpers ----------------
__device__ __forceinline__ unsigned long long packdup(float v) {
    unsigned long long r;
    asm("mov.b64 %0, {%1, %1};" : "=l"(r) : "f"(v));
    return r;
}
__device__ __forceinline__ float2 unpack2(unsigned long long v) {
    float2 r;
    asm("mov.b64 {%0, %1}, %2;" : "=f"(r.x), "=f"(r.y) : "l"(v));
    return r;
}
#define FFMA2(d, a, b) asm("fma.rn.f32x2 %0, %1, %2, %3;" : "=l"(d) : "l"(a), "l"(b), "l"(d))

#define CP_ASYNC16(dst, src) \
    asm volatile("cp.async.cg.shared.global [%0], [%1], 16;" :: "r"(dst), "l"(src))
#define CP_COMMIT() asm volatile("cp.async.commit_group;")
#define CP_WAIT2()  asm volatile("cp.async.wait_group 2;" ::: "memory")

#define LDSM_X4_T(d0, d1, d2, d3, addr)                                        \
    asm volatile("ldmatrix.sync.aligned.m8n8.x4.trans.shared.b16 "             \
                 "{%0,%1,%2,%3}, [%4];"                                        \
                 : "=r"(d0), "=r"(d1), "=r"(d2), "=r"(d3) : "r"(addr))

#define MMA_F16(D, A, B0, B1)                                                 \
    asm("mma.sync.aligned.m16n8k16.row.col.f32.f16.f16.f32 "                  \
        "{%0,%1,%2,%3},{%4,%5,%6,%7},{%8,%9},{%0,%1,%2,%3};"                  \
        : "+f"((D)[0]), "+f"((D)[1]), "+f"((D)[2]), "+f"((D)[3])              \
        : "r"((A)[0]), "r"((A)[1]), "r"((A)[2]), "r"((A)[3]),                 \
          "r"(B0), "r"(B1))

// ============================================================
// Kernel A: Wh = x@W, attention dots, exp tables (fp16), Wh fp16 [j][f].
// 256 blocks x 512 threads; 32 rows/block, 16 threads/row (k-split 2x64).
// ============================================================
#define XSTR 132
#define PREP_SMEM ((8192 + 32 * XSTR + 128) * 4)

__global__ void __launch_bounds__(512) gat_prep(const float* __restrict__ x,
                                                const float* __restrict__ W,
                                                const float* __restrict__ a)
{
    extern __shared__ float psm[];
    float* wS = psm;                    // [128][64]
    float* xS = psm + 8192;             // [32][XSTR]
    float* aS = psm + 8192 + 32 * XSTR;

    const int t = threadIdx.x;
    const int row0 = blockIdx.x * 32;

    #pragma unroll
    for (int q = 0; q < 4; q++) {
        int idx = (q * 512 + t) * 4;
        *(float4*)&wS[idx] = *(const float4*)&W[idx];
    }
    const float* xb = x + (size_t)row0 * 128;
    #pragma unroll
    for (int q = 0; q < 2; q++) {
        int flat = (q * 512 + t) * 4;
        int r = flat >> 7, c = flat & 127;
        *(float4*)&xS[r * XSTR + c] = *(const float4*)&xb[flat];
    }
    if (t < 32) *(float4*)&aS[t * 4] = *(const float4*)&a[t * 4];
    __syncthreads();

    const int r  = t >> 4;          // row within block (0..31)
    const int c  = t & 15;          // 16 threads per row
    const int kh = c >> 3;          // k-half (0: k<64, 1: k>=64)
    const int cc = c & 7;           // f-octet
    const int kbase = kh * 64;

    unsigned long long acc4[4] = {0ull, 0ull, 0ull, 0ull};

    #pragma unroll 8
    for (int kk = 0; kk < 64; kk++) {
        unsigned long long xd = packdup(xS[r * XSTR + kbase + kk]);
        const unsigned long long* w =
            reinterpret_cast<const unsigned long long*>(&wS[(kbase + kk) * 64]);
        FFMA2(acc4[0], xd, w[cc]);
        FFMA2(acc4[1], xd, w[8 + cc]);
        FFMA2(acc4[2], xd, w[16 + cc]);
        FFMA2(acc4[3], xd, w[24 + cc]);
    }

    // combine the two k-halves (lanes differing in bit 3)
    float wv[8];
    #pragma unroll
    for (int m = 0; m < 4; m++) {
        float2 u = unpack2(acc4[m]);
        u.x += __shfl_xor_sync(0xffffffffu, u.x, 8);
        u.y += __shfl_xor_sync(0xffffffffu, u.y, 8);
        wv[2 * m] = u.x; wv[2 * m + 1] = u.y;
    }

    float p1 = 0.f, p2 = 0.f;
    const int row = row0 + r;
    #pragma unroll
    for (int m = 0; m < 4; m++) {
        const int col = 16 * m + 2 * cc;
        p1 += wv[2 * m] * aS[col]      + wv[2 * m + 1] * aS[col + 1];
        p2 += wv[2 * m] * aS[64 + col] + wv[2 * m + 1] * aS[64 + col + 1];
        if (kh == 0)
            *(__half2*)&g_Wh_h[(size_t)row * 64 + col] =
                __floats2half2_rn(wv[2 * m], wv[2 * m + 1]);
    }
    p1 += __shfl_xor_sync(0xffffffffu, p1, 1);
    p1 += __shfl_xor_sync(0xffffffffu, p1, 2);
    p1 += __shfl_xor_sync(0xffffffffu, p1, 4);
    p2 += __shfl_xor_sync(0xffffffffu, p2, 1);
    p2 += __shfl_xor_sync(0xffffffffu, p2, 2);
    p2 += __shfl_xor_sync(0xffffffffu, p2, 4);

    if (c == 0) {
        g_E1P[row]  = make_float2(__expf(p1), __expf(0.2f * p1));
        g_E2XH[row] = __float2half(__expf(p2));
        g_E2YH[row] = __float2half(__expf(0.2f * p2));
    }
}

// ============================================================
// Kernel B: 3-stage cp.async ring (adj+Wh) + fp16 MMA; den on ALU pipe.
// grid (64, 16) x 128 threads (4 warps), 3 blocks/SM. 32 MMAs/warp/tile.
// ============================================================
__global__ void __launch_bounds__(128, 3) gat_attn(const float* __restrict__ adj)
{
    extern __shared__ char smem[];
    const int t = threadIdx.x, lane = t & 31, warp = t >> 5;
    const int ib = blockIdx.x, js = blockIdx.y;
    const int i_base = ib * TI, i_warp = i_base + warp * 32;
    const int j0 = js * JRANGE;
    const int r0 = lane >> 2, c0 = (lane & 3) * 2;

    const uint32_t sb = (uint32_t)__cvta_generic_to_shared(smem);

    // staging maps (fully coalesced 128B chunks)
    const int arow = t >> 3, aseg = t & 7;
    const float* adj_base = adj + (size_t)(i_base + arow) * N + j0 + aseg * 4;
    const __half* wh_base = g_Wh_h + (size_t)(j0 + arow) * 64 + aseg * 8;

#define PREFETCH(tt)                                                           \
    do {                                                                       \
        const uint32_t st_ = sb + ((tt) % 3) * STAGE_B;                        \
        const float* as_ = adj_base + (tt) * TJ;                               \
        _Pragma("unroll")                                                      \
        for (int q_ = 0; q_ < 8; q_++)                                         \
            CP_ASYNC16(st_ + (q_ * 16 + arow) * (ADJ_STR * 4) + aseg * 16,     \
                       as_ + (size_t)(q_ * 16) * N);                           \
        const uint32_t wst_ = st_ + STAGE_ADJ_B;                               \
        const __half* ws_ = wh_base + (size_t)((tt) * TJ) * 64;                \
        CP_ASYNC16(wst_ + arow * 144 + aseg * 16, ws_);                        \
        CP_ASYNC16(wst_ + (16 + arow) * 144 + aseg * 16, ws_ + 16 * 64);       \
        CP_COMMIT();                                                           \
    } while (0)

    // e1 fp16 splats (invariant)
    __half2 e1x2[2][2], e1y2[2][2];
    #pragma unroll
    for (int mt = 0; mt < 2; mt++)
        #pragma unroll
        for (int aa = 0; aa < 2; aa++) {
            float2 e1f = g_E1P[i_warp + mt * 16 + aa * 8 + r0];
            e1x2[mt][aa] = __half2half2(__float2half(e1f.x));
            e1y2[mt][aa] = __half2half2(__float2half(e1f.y));
        }

    float acc[2][8][4];
    #pragma unroll
    for (int mt = 0; mt < 2; mt++)
        #pragma unroll
        for (int nt = 0; nt < 8; nt++)
            #pragma unroll
            for (int e = 0; e < 4; e++) acc[mt][nt][e] = 0.f;
    float den4[2][2] = {{0.f, 0.f}, {0.f, 0.f}};

    // ldmatrix lane map (x4.trans)
    const int mm = lane >> 3;
    const int ldsm_row = (mm & 1) * 8 + (lane & 7);
    const int ldsm_f   = mm >> 1;

    PREFETCH(0); PREFETCH(1); PREFETCH(2);

    #pragma unroll 1
    for (int it = 0; it < NT; it++) {
        const int s = it % 3;
        const int jt = j0 + it * TJ;
        CP_WAIT2();
        __syncthreads();

        // ---- e2 fp16 pair loads (L1-hot) ----
        __half2 ex2[2][2], ey2[2][2];
        #pragma unroll
        for (int kt = 0; kt < 2; kt++)
            #pragma unroll
            for (int hh = 0; hh < 2; hh++) {
                const int jj = jt + kt * 16 + hh * 8 + c0;
                ex2[kt][hh] = *(const __half2*)&g_E2XH[jj];
                ey2[kt][hh] = *(const __half2*)&g_E2YH[jj];
            }

        // ---- A fragments (P) from smem adj ----
        const float* adjS = (const float*)(smem + s * STAGE_B);
        uint32_t afr[2][2][4];
        #pragma unroll
        for (int mt = 0; mt < 2; mt++)
            #pragma unroll
            for (int kt = 0; kt < 2; kt++)
                #pragma unroll
                for (int aa = 0; aa < 2; aa++)
                    #pragma unroll
                    for (int hh = 0; hh < 2; hh++) {
                        const int R = warp * 32 + mt * 16 + aa * 8 + r0;
                        float2 ad = *(const float2*)&adjS[R * ADJ_STR +
                                                          kt * 16 + hh * 8 + c0];
                        __half2 ah = __floats2half2_rn(ad.x, ad.y);
                        __half2 u  = __hmul2(e1x2[mt][aa], ex2[kt][hh]);
                        __half2 v  = __hmul2(e1y2[mt][aa], ey2[kt][hh]);
                        __half2 p  = __hmul2(__hmax2(u, v), ah);
                        afr[mt][kt][aa + 2 * hh] = *(uint32_t*)&p;
                    }

        // ---- den on ALU pipe (tree of the same rounded p values) ----
        #pragma unroll
        for (int mt = 0; mt < 2; mt++)
            #pragma unroll
            for (int aa = 0; aa < 2; aa++) {
                __half2 s0 = __hadd2(*(__half2*)&afr[mt][0][aa],
                                     *(__half2*)&afr[mt][0][aa + 2]);
                __half2 s1 = __hadd2(*(__half2*)&afr[mt][1][aa],
                                     *(__half2*)&afr[mt][1][aa + 2]);
                float2 f0 = __half22float2(s0);
                float2 f1 = __half22float2(s1);
                den4[mt][aa] += (f0.x + f0.y) + (f1.x + f1.y);
            }

        // ---- B fragments to regs (LDSM from Wh stage s) ----
        uint32_t bq[2][4][4];
        #pragma unroll
        for (int kt = 0; kt < 2; kt++) {
            const uint32_t abase = sb + s * STAGE_B + STAGE_ADJ_B
                                   + (kt * 16 + ldsm_row) * 144 + ldsm_f * 16;
            #pragma unroll
            for (int p = 0; p < 4; p++)
                LDSM_X4_T(bq[kt][p][0], bq[kt][p][1], bq[kt][p][2], bq[kt][p][3],
                          abase + p * 32);
        }
        __syncthreads();   // all warps done with stage s

        // ---- prefetch tile it+3 into stage s ----
        if (it + 3 < NT) { PREFETCH(it + 3); } else { CP_COMMIT(); }

        // ---- 32 MMAs (all operands in registers) ----
        #pragma unroll
        for (int kt = 0; kt < 2; kt++)
            #pragma unroll
            for (int p = 0; p < 4; p++) {
                MMA_F16(acc[0][2 * p],     afr[0][kt], bq[kt][p][0], bq[kt][p][1]);
                MMA_F16(acc[0][2 * p + 1], afr[0][kt], bq[kt][p][2], bq[kt][p][3]);
                MMA_F16(acc[1][2 * p],     afr[1][kt], bq[kt][p][0], bq[kt][p][1]);
                MMA_F16(acc[1][2 * p + 1], afr[1][kt], bq[kt][p][2], bq[kt][p][3]);
            }
    }

    // ---- epilogue ----
    float* ob = g_acc[js];
    #pragma unroll
    for (int mt = 0; mt < 2; mt++) {
        const int ir = i_warp + mt * 16 + r0;
        #pragma unroll
        for (int nt = 0; nt < 8; nt++) {
            const int fc = nt * 8 + c0;
            *(float2*)&ob[(size_t)ir * FOUT + fc] =
                make_float2(acc[mt][nt][0], acc[mt][nt][1]);
            *(float2*)&ob[(size_t)(ir + 8) * FOUT + fc] =
                make_float2(acc[mt][nt][2], acc[mt][nt][3]);
        }
    }
    #pragma unroll
    for (int mt = 0; mt < 2; mt++)
        #pragma unroll
        for (int aa = 0; aa < 2; aa++) {
            float d = den4[mt][aa];
            d += __shfl_xor_sync(0xffffffffu, d, 1);
            d += __shfl_xor_sync(0xffffffffu, d, 2);
            if ((lane & 3) == 0)
                g_den[js][i_warp + mt * 16 + aa * 8 + r0] = d;
        }
}

// ============================================================
// Kernel C: combine partials, normalize, ELU.
// ============================================================
__global__ void __launch_bounds__(256) gat_final(float* __restrict__ out)
{
    const int idx = blockIdx.x * 256 + threadIdx.x;   // < N*FOUT
    const int i = idx >> 6;
    float d = 0.f, v = 0.f;
    #pragma unroll
    for (int s = 0; s < JSPLIT; s++) {
        d += g_den[s][i];
        v += g_acc[s][idx];
    }
    float h = v / d;
    out[idx] = (h > 0.f) ? h : expm1f(h);
}

// ============================================================
extern "C" void kernel_launch(void* const* d_in, const int* in_sizes, int n_in,
                              void* d_out, int out_size)
{
    const float* x   = (const float*)d_in[0];
    const float* adj = (const float*)d_in[1];
    const float* W   = (const float*)d_in[2];
    const float* a   = (const float*)d_in[3];
    float* out = (float*)d_out;

    cudaFuncSetAttribute(gat_prep, cudaFuncAttributeMaxDynamicSharedMemorySize,
                         PREP_SMEM);
    cudaFuncSetAttribute(gat_attn, cudaFuncAttributeMaxDynamicSharedMemorySize,
                         SMEMB_BYTES);

    gat_prep<<<N / 32, 512, PREP_SMEM>>>(x, W, a);
    gat_attn<<<dim3(N / TI, JSPLIT), TI, SMEMB_BYTES>>>(adj);
    gat_final<<<(N * FOUT) / 256, 256>>>(out);
}

// round 11
// speedup vs baseline: 1.0433x; 1.0433x over previous
#include <cuda_runtime.h>
#include <cuda_fp16.h>
#include <cstdint>

// GAT layer, N=8192, Fin=128, Fout=64.
// inputs: x [N,128] f32, adj [N,N] f32 (0/1), W [128,64] f32, a [128,1] f32
// output: [N,64] f32

#define N      8192
#define FOUT   64
#define TI     128
#define TJ     32
#define JSPLIT 8
#define JRANGE (N / JSPLIT)     // 1024
#define NT     (JRANGE / TJ)    // 32

#define ADJ_STR 40                        // floats per adj smem row (160 B, conflict-free)
#define WH_STR  72                        // halves per Wh smem row (144 B)
#define STAGE_ADJ_B (TI * ADJ_STR * 4)    // 20480
#define STAGE_WH_B  (TJ * WH_STR * 2)     // 4608
#define STAGE_B     (STAGE_ADJ_B + STAGE_WH_B)   // 25088
#define NSTAGE 3
#define SMEMB_BYTES (NSTAGE * STAGE_B)    // 75264

// ---------------- device scratch ----------------
__device__ float2 g_E1P[N];                  // (e^Wh1, e^{0.2 Wh1}) fp32
__device__ __half g_E2XH[N];                 // fp16 e^Wh2
__device__ __half g_E2YH[N];                 // fp16 e^{0.2 Wh2}
__device__ __half g_Wh_h[N * FOUT];          // Wh [j][f] fp16
__device__ float  g_acc[JSPLIT][N * FOUT];   // partial numerators [js][i][f]
__device__ float  g_den[JSPLIT][N];          // partial denominators

// ---------------- helpers ----------------
__device__ __forceinline__ unsigned long long packdup(float v) {
    unsigned long long r;
    asm("mov.b64 %0, {%1, %1};" : "=l"(r) : "f"(v));
    return r;
}
__device__ __forceinline__ float2 unpack2(unsigned long long v) {
    float2 r;
    asm("mov.b64 {%0, %1}, %2;" : "=f"(r.x), "=f"(r.y) : "l"(v));
    return r;
}
#define FFMA2(d, a, b) asm("fma.rn.f32x2 %0, %1, %2, %3;" : "=l"(d) : "l"(a), "l"(b), "l"(d))

#define CP_ASYNC16(dst, src) \
    asm volatile("cp.async.cg.shared.global [%0], [%1], 16;" :: "r"(dst), "l"(src))
#define CP_COMMIT() asm volatile("cp.async.commit_group;")
#define CP_WAIT2()  asm volatile("cp.async.wait_group 2;" ::: "memory")

#define LDSM_X4_T(d0, d1, d2, d3, addr)                                        \
    asm volatile("ldmatrix.sync.aligned.m8n8.x4.trans.shared.b16 "             \
                 "{%0,%1,%2,%3}, [%4];"                                        \
                 : "=r"(d0), "=r"(d1), "=r"(d2), "=r"(d3) : "r"(addr))

#define MMA_F16(D, A, B0, B1)                                                 \
    asm("mma.sync.aligned.m16n8k16.row.col.f32.f16.f16.f32 "                  \
        "{%0,%1,%2,%3},{%4,%5,%6,%7},{%8,%9},{%0,%1,%2,%3};"                  \
        : "+f"((D)[0]), "+f"((D)[1]), "+f"((D)[2]), "+f"((D)[3])              \
        : "r"((A)[0]), "r"((A)[1]), "r"((A)[2]), "r"((A)[3]),                 \
          "r"(B0), "r"(B1))

// ============================================================
// Kernel A: Wh = x@W, attention dots, exp tables (fp16), Wh fp16 [j][f].
// 256 blocks x 256 threads; 32 rows/block, 8 threads/row. (proven 14.3us)
// ============================================================
#define XSTR 132
#define PREP_SMEM ((8192 + 32 * XSTR + 128) * 4)

__global__ void __launch_bounds__(256) gat_prep(const float* __restrict__ x,
                                                const float* __restrict__ W,
                                                const float* __restrict__ a)
{
    extern __shared__ float psm[];
    float* wS = psm;                    // [128][64]
    float* xS = psm + 8192;             // [32][XSTR]
    float* aS = psm + 8192 + 32 * XSTR;

    const int t = threadIdx.x;
    const int row0 = blockIdx.x * 32;

    #pragma unroll
    for (int q = 0; q < 8; q++) {
        int idx = (q * 256 + t) * 4;
        *(float4*)&wS[idx] = *(const float4*)&W[idx];
    }
    const float* xb = x + (size_t)row0 * 128;
    #pragma unroll
    for (int q = 0; q < 4; q++) {
        int flat = (q * 256 + t) * 4;
        int r = flat >> 7, c = flat & 127;
        *(float4*)&xS[r * XSTR + c] = *(const float4*)&xb[flat];
    }
    if (t < 32) *(float4*)&aS[t * 4] = *(const float4*)&a[t * 4];
    __syncthreads();

    const int r = t >> 3, c = t & 7;
    unsigned long long acc4[4] = {0ull, 0ull, 0ull, 0ull};

    #pragma unroll 8
    for (int kk = 0; kk < 128; kk++) {
        unsigned long long xd = packdup(xS[r * XSTR + kk]);
        const unsigned long long* w =
            reinterpret_cast<const unsigned long long*>(&wS[kk * 64]);
        FFMA2(acc4[0], xd, w[c]);
        FFMA2(acc4[1], xd, w[8 + c]);
        FFMA2(acc4[2], xd, w[16 + c]);
        FFMA2(acc4[3], xd, w[24 + c]);
    }

    float p1 = 0.f, p2 = 0.f;
    const int row = row0 + r;
    #pragma unroll
    for (int m = 0; m < 4; m++) {
        float2 u = unpack2(acc4[m]);
        const int col = 16 * m + 2 * c;
        p1 += u.x * aS[col]      + u.y * aS[col + 1];
        p2 += u.x * aS[64 + col] + u.y * aS[64 + col + 1];
        *(__half2*)&g_Wh_h[(size_t)row * 64 + col] = __floats2half2_rn(u.x, u.y);
    }
    p1 += __shfl_xor_sync(0xffffffffu, p1, 1);
    p1 += __shfl_xor_sync(0xffffffffu, p1, 2);
    p1 += __shfl_xor_sync(0xffffffffu, p1, 4);
    p2 += __shfl_xor_sync(0xffffffffu, p2, 1);
    p2 += __shfl_xor_sync(0xffffffffu, p2, 2);
    p2 += __shfl_xor_sync(0xffffffffu, p2, 4);

    if (c == 0) {
        g_E1P[row]  = make_float2(__expf(p1), __expf(0.2f * p1));
        g_E2XH[row] = __float2half(__expf(p2));
        g_E2YH[row] = __float2half(__expf(0.2f * p2));
    }
}

// ============================================================
// Kernel B: 3-stage cp.async ring (adj+Wh) + fp16 MMA (den via ones column).
// grid (64, 8) x 128 threads (4 warps), 3 blocks/SM. 34 MMAs/warp/tile.
// ============================================================
__global__ void __launch_bounds__(128, 3) gat_attn(const float* __restrict__ adj)
{
    extern __shared__ char smem[];
    const int t = threadIdx.x, lane = t & 31, warp = t >> 5;
    const int ib = blockIdx.x, js = blockIdx.y;
    const int i_base = ib * TI, i_warp = i_base + warp * 32;
    const int j0 = js * JRANGE;
    const int r0 = lane >> 2, c0 = (lane & 3) * 2;

    const uint32_t sb = (uint32_t)__cvta_generic_to_shared(smem);

    // staging maps (fully coalesced 128B chunks)
    const int arow = t >> 3, aseg = t & 7;
    const float* adj_base = adj + (size_t)(i_base + arow) * N + j0 + aseg * 4;
    const __half* wh_base = g_Wh_h + (size_t)(j0 + arow) * 64 + aseg * 8;

#define PREFETCH(tt)                                                           \
    do {                                                                       \
        const uint32_t st_ = sb + ((tt) % 3) * STAGE_B;                        \
        const float* as_ = adj_base + (tt) * TJ;                               \
        _Pragma("unroll")                                                      \
        for (int q_ = 0; q_ < 8; q_++)                                         \
            CP_ASYNC16(st_ + (q_ * 16 + arow) * (ADJ_STR * 4) + aseg * 16,     \
                       as_ + (size_t)(q_ * 16) * N);                           \
        const uint32_t wst_ = st_ + STAGE_ADJ_B;                               \
        const __half* ws_ = wh_base + (size_t)((tt) * TJ) * 64;                \
        CP_ASYNC16(wst_ + arow * 144 + aseg * 16, ws_);                        \
        CP_ASYNC16(wst_ + (16 + arow) * 144 + aseg * 16, ws_ + 16 * 64);       \
        CP_COMMIT();                                                           \
    } while (0)

    // e1 fp16 splats (invariant)
    __half2 e1x2[2][2], e1y2[2][2];
    #pragma unroll
    for (int mt = 0; mt < 2; mt++)
        #pragma unroll
        for (int aa = 0; aa < 2; aa++) {
            float2 e1f = g_E1P[i_warp + mt * 16 + aa * 8 + r0];
            e1x2[mt][aa] = __half2half2(__float2half(e1f.x));
            e1y2[mt][aa] = __half2half2(__float2half(e1f.y));
        }

    float acc[2][8][4];
    float accden[2][4];
    #pragma unroll
    for (int mt = 0; mt < 2; mt++) {
        #pragma unroll
        for (int nt = 0; nt < 8; nt++)
            #pragma unroll
            for (int e = 0; e < 4; e++) acc[mt][nt][e] = 0.f;
        #pragma unroll
        for (int e = 0; e < 4; e++) accden[mt][e] = 0.f;
    }
    const uint32_t bones = (r0 == 0) ? 0x3C003C00u : 0u;   // fp16 ones column

    // ldmatrix lane map (x4.trans)
    const int mm = lane >> 3;
    const int ldsm_row = (mm & 1) * 8 + (lane & 7);
    const int ldsm_f   = mm >> 1;

    PREFETCH(0); PREFETCH(1); PREFETCH(2);

    #pragma unroll 1
    for (int it = 0; it < NT; it++) {
        const int s = it % 3;
        const int jt = j0 + it * TJ;
        CP_WAIT2();
        __syncthreads();

        // ---- e2 fp16 pair loads (L1-hot) ----
        __half2 ex2[2][2], ey2[2][2];
        #pragma unroll
        for (int kt = 0; kt < 2; kt++)
            #pragma unroll
            for (int hh = 0; hh < 2; hh++) {
                const int jj = jt + kt * 16 + hh * 8 + c0;
                ex2[kt][hh] = *(const __half2*)&g_E2XH[jj];
                ey2[kt][hh] = *(const __half2*)&g_E2YH[jj];
            }

        // ---- A fragments (P) from smem adj (conflict-free float2 LDS) ----
        const float* adjS = (const float*)(smem + s * STAGE_B);
        uint32_t afr[2][2][4];
        #pragma unroll
        for (int mt = 0; mt < 2; mt++)
            #pragma unroll
            for (int kt = 0; kt < 2; kt++)
                #pragma unroll
                for (int aa = 0; aa < 2; aa++)
                    #pragma unroll
                    for (int hh = 0; hh < 2; hh++) {
                        const int R = warp * 32 + mt * 16 + aa * 8 + r0;
                        float2 ad = *(const float2*)&adjS[R * ADJ_STR +
                                                          kt * 16 + hh * 8 + c0];
                        __half2 ah = __floats2half2_rn(ad.x, ad.y);
                        __half2 u  = __hmul2(e1x2[mt][aa], ex2[kt][hh]);
                        __half2 v  = __hmul2(e1y2[mt][aa], ey2[kt][hh]);
                        __half2 p  = __hmul2(__hmax2(u, v), ah);
                        afr[mt][kt][aa + 2 * hh] = *(uint32_t*)&p;
                    }

        // ---- B fragments to regs (LDSM from Wh stage s) ----
        uint32_t bq[2][4][4];
        #pragma unroll
        for (int kt = 0; kt < 2; kt++) {
            const uint32_t abase = sb + s * STAGE_B + STAGE_ADJ_B
                                   + (kt * 16 + ldsm_row) * 144 + ldsm_f * 16;
            #pragma unroll
            for (int p = 0; p < 4; p++)
                LDSM_X4_T(bq[kt][p][0], bq[kt][p][1], bq[kt][p][2], bq[kt][p][3],
                          abase + p * 32);
        }
        __syncthreads();   // all warps done with stage s

        // ---- prefetch tile it+3 into stage s ----
        if (it + 3 < NT) { PREFETCH(it + 3); } else { CP_COMMIT(); }

        // ---- MMAs (all operands in registers) ----
        #pragma unroll
        for (int kt = 0; kt < 2; kt++) {
            #pragma unroll
            for (int p = 0; p < 4; p++) {
                MMA_F16(acc[0][2 * p],     afr[0][kt], bq[kt][p][0], bq[kt][p][1]);
                MMA_F16(acc[0][2 * p + 1], afr[0][kt], bq[kt][p][2], bq[kt][p][3]);
                MMA_F16(acc[1][2 * p],     afr[1][kt], bq[kt][p][0], bq[kt][p][1]);
                MMA_F16(acc[1][2 * p + 1], afr[1][kt], bq[kt][p][2], bq[kt][p][3]);
            }
            MMA_F16(accden[0], afr[0][kt], bones, bones);
            MMA_F16(accden[1], afr[1][kt], bones, bones);
        }
    }

    // ---- epilogue ----
    float* ob = g_acc[js];
    #pragma unroll
    for (int mt = 0; mt < 2; mt++) {
        const int ir = i_warp + mt * 16 + r0;
        #pragma unroll
        for (int nt = 0; nt < 8; nt++) {
            const int fc = nt * 8 + c0;
            *(float2*)&ob[(size_t)ir * FOUT + fc] =
                make_float2(acc[mt][nt][0], acc[mt][nt][1]);
            *(float2*)&ob[(size_t)(ir + 8) * FOUT + fc] =
                make_float2(acc[mt][nt][2], acc[mt][nt][3]);
        }
    }
    if ((lane & 3) == 0) {
        #pragma unroll
        for (int mt = 0; mt < 2; mt++) {
            g_den[js][i_warp + mt * 16 + r0]     = accden[mt][0];
            g_den[js][i_warp + mt * 16 + 8 + r0] = accden[mt][2];
        }
    }
}

// ============================================================
// Kernel C: combine partials, normalize, ELU.
// ============================================================
__global__ void __launch_bounds__(256) gat_final(float* __restrict__ out)
{
    const int idx = blockIdx.x * 256 + threadIdx.x;   // < N*FOUT
    const int i = idx >> 6;
    float d = 0.f, v = 0.f;
    #pragma unroll
    for (int s = 0; s < JSPLIT; s++) {
        d += g_den[s][i];
        v += g_acc[s][idx];
    }
    float h = v / d;
    out[idx] = (h > 0.f) ? h : expm1f(h);
}

// ============================================================
extern "C" void kernel_launch(void* const* d_in, const int* in_sizes, int n_in,
                              void* d_out, int out_size)
{
    const float* x   = (const float*)d_in[0];
    const float* adj = (const float*)d_in[1];
    const float* W   = (const float*)d_in[2];
    const float* a   = (const float*)d_in[3];
    float* out = (float*)d_out;

    cudaFuncSetAttribute(gat_prep, cudaFuncAttributeMaxDynamicSharedMemorySize,
                         PREP_SMEM);
    cudaFuncSetAttribute(gat_attn, cudaFuncAttributeMaxDynamicSharedMemorySize,
                         SMEMB_BYTES);

    gat_prep<<<N / 32, 256, PREP_SMEM>>>(x, W, a);
    gat_attn<<<dim3(N / TI, JSPLIT), TI, SMEMB_BYTES>>>(adj);
    gat_final<<<(N * FOUT) / 256, 256>>>(out);
}

// round 12
// speedup vs baseline: 1.1044x; 1.0586x over previous
#include <cuda_runtime.h>
#include <cuda_fp16.h>
#include <cstdint>

// GAT layer, N=8192, Fin=128, Fout=64.
// inputs: x [N,128] f32, adj [N,N] f32 (0/1), W [128,64] f32, a [128,1] f32
// output: [N,64] f32

#define N      8192
#define FOUT   64
#define TI     128
#define TJ     32
#define JSPLIT 16
#define JRANGE (N / JSPLIT)     // 512
#define NT     (JRANGE / TJ)    // 16

#define ADJ_STR 40                        // floats per adj smem row (160 B, conflict-free)
#define WH_STR  72                        // halves per Wh smem row (144 B)
#define STAGE_ADJ_B (TI * ADJ_STR * 4)    // 20480
#define STAGE_WH_B  (TJ * WH_STR * 2)     // 4608
#define STAGE_B     (STAGE_ADJ_B + STAGE_WH_B)   // 25088
#define NSTAGE 3
#define SMEMB_BYTES (NSTAGE * STAGE_B)    // 75264

// ---------------- device scratch ----------------
__device__ float2 g_E1P[N];                  // (e^Wh1, e^{0.2 Wh1}) fp32
__device__ __half g_E2XH[N];                 // fp16 e^Wh2
__device__ __half g_E2YH[N];                 // fp16 e^{0.2 Wh2}
__device__ __half g_Wh_h[N * FOUT];          // Wh [j][f] fp16
__device__ float  g_acc[JSPLIT][N * FOUT];   // partial numerators [js][i][f]
__device__ float  g_den[JSPLIT][N];          // partial denominators

// ---------------- helpers ----------------
__device__ __forceinline__ unsigned long long packdup(float v) {
    unsigned long long r;
    asm("mov.b64 %0, {%1, %1};" : "=l"(r) : "f"(v));
    return r;
}
__device__ __forceinline__ float2 unpack2(unsigned long long v) {
    float2 r;
    asm("mov.b64 {%0, %1}, %2;" : "=f"(r.x), "=f"(r.y) : "l"(v));
    return r;
}
#define FFMA2(d, a, b) asm("fma.rn.f32x2 %0, %1, %2, %3;" : "=l"(d) : "l"(a), "l"(b), "l"(d))

#define CP_ASYNC16(dst, src) \
    asm volatile("cp.async.cg.shared.global [%0], [%1], 16;" :: "r"(dst), "l"(src))
#define CP_COMMIT() asm volatile("cp.async.commit_group;")
#define CP_WAIT2()  asm volatile("cp.async.wait_group 2;" ::: "memory")

#define LDSM_X4_T(d0, d1, d2, d3, addr)                                        \
    asm volatile("ldmatrix.sync.aligned.m8n8.x4.trans.shared.b16 "             \
                 "{%0,%1,%2,%3}, [%4];"                                        \
                 : "=r"(d0), "=r"(d1), "=r"(d2), "=r"(d3) : "r"(addr))

#define MMA_F16(D, A, B0, B1)                                                 \
    asm("mma.sync.aligned.m16n8k16.row.col.f32.f16.f16.f32 "                  \
        "{%0,%1,%2,%3},{%4,%5,%6,%7},{%8,%9},{%0,%1,%2,%3};"                  \
        : "+f"((D)[0]), "+f"((D)[1]), "+f"((D)[2]), "+f"((D)[3])              \
        : "r"((A)[0]), "r"((A)[1]), "r"((A)[2]), "r"((A)[3]),                 \
          "r"(B0), "r"(B1))

// ============================================================
// Kernel A: Wh = x@W, attention dots, exp tables (fp16), Wh fp16 [j][f].
// 256 blocks x 256 threads; 32 rows/block, 8 threads/row.
// ILP: 8 accumulator chains (k-split in-thread, depth 64).
// ============================================================
#define XSTR 132
#define PREP_SMEM ((8192 + 32 * XSTR + 128) * 4)

__global__ void __launch_bounds__(256) gat_prep(const float* __restrict__ x,
                                                const float* __restrict__ W,
                                                const float* __restrict__ a)
{
    extern __shared__ float psm[];
    float* wS = psm;                    // [128][64]
    float* xS = psm + 8192;             // [32][XSTR]
    float* aS = psm + 8192 + 32 * XSTR;

    const int t = threadIdx.x;
    const int row0 = blockIdx.x * 32;

    #pragma unroll
    for (int q = 0; q < 8; q++) {
        int idx = (q * 256 + t) * 4;
        *(float4*)&wS[idx] = *(const float4*)&W[idx];
    }
    const float* xb = x + (size_t)row0 * 128;
    #pragma unroll
    for (int q = 0; q < 4; q++) {
        int flat = (q * 256 + t) * 4;
        int r = flat >> 7, c = flat & 127;
        *(float4*)&xS[r * XSTR + c] = *(const float4*)&xb[flat];
    }
    if (t < 32) *(float4*)&aS[t * 4] = *(const float4*)&a[t * 4];
    __syncthreads();

    const int r = t >> 3, c = t & 7;
    unsigned long long accA[4] = {0ull, 0ull, 0ull, 0ull};   // k < 64
    unsigned long long accB[4] = {0ull, 0ull, 0ull, 0ull};   // k >= 64

    #pragma unroll 8
    for (int kk = 0; kk < 64; kk++) {
        unsigned long long xd0 = packdup(xS[r * XSTR + kk]);
        unsigned long long xd1 = packdup(xS[r * XSTR + 64 + kk]);
        const unsigned long long* w0 =
            reinterpret_cast<const unsigned long long*>(&wS[kk * 64]);
        const unsigned long long* w1 =
            reinterpret_cast<const unsigned long long*>(&wS[(64 + kk) * 64]);
        FFMA2(accA[0], xd0, w0[c]);
        FFMA2(accA[1], xd0, w0[8 + c]);
        FFMA2(accA[2], xd0, w0[16 + c]);
        FFMA2(accA[3], xd0, w0[24 + c]);
        FFMA2(accB[0], xd1, w1[c]);
        FFMA2(accB[1], xd1, w1[8 + c]);
        FFMA2(accB[2], xd1, w1[16 + c]);
        FFMA2(accB[3], xd1, w1[24 + c]);
    }

    float p1 = 0.f, p2 = 0.f;
    const int row = row0 + r;
    #pragma unroll
    for (int m = 0; m < 4; m++) {
        float2 uA = unpack2(accA[m]);
        float2 uB = unpack2(accB[m]);
        float2 u = make_float2(uA.x + uB.x, uA.y + uB.y);
        const int col = 16 * m + 2 * c;
        p1 += u.x * aS[col]      + u.y * aS[col + 1];
        p2 += u.x * aS[64 + col] + u.y * aS[64 + col + 1];
        *(__half2*)&g_Wh_h[(size_t)row * 64 + col] = __floats2half2_rn(u.x, u.y);
    }
    p1 += __shfl_xor_sync(0xffffffffu, p1, 1);
    p1 += __shfl_xor_sync(0xffffffffu, p1, 2);
    p1 += __shfl_xor_sync(0xffffffffu, p1, 4);
    p2 += __shfl_xor_sync(0xffffffffu, p2, 1);
    p2 += __shfl_xor_sync(0xffffffffu, p2, 2);
    p2 += __shfl_xor_sync(0xffffffffu, p2, 4);

    if (c == 0) {
        g_E1P[row]  = make_float2(__expf(p1), __expf(0.2f * p1));
        g_E2XH[row] = __float2half(__expf(p2));
        g_E2YH[row] = __float2half(__expf(0.2f * p2));
    }
}

// ============================================================
// Kernel B: 3-stage cp.async ring (adj+Wh) + fp16 MMA (den via ones column).
// grid (64, 16) x 128 threads (4 warps), 3 blocks/SM. 34 MMAs/warp/tile.
// (byte-identical to the 92.6us R9 version)
// ============================================================
__global__ void __launch_bounds__(128, 3) gat_attn(const float* __restrict__ adj)
{
    extern __shared__ char smem[];
    const int t = threadIdx.x, lane = t & 31, warp = t >> 5;
    const int ib = blockIdx.x, js = blockIdx.y;
    const int i_base = ib * TI, i_warp = i_base + warp * 32;
    const int j0 = js * JRANGE;
    const int r0 = lane >> 2, c0 = (lane & 3) * 2;

    const uint32_t sb = (uint32_t)__cvta_generic_to_shared(smem);

    // staging maps (fully coalesced 128B chunks)
    const int arow = t >> 3, aseg = t & 7;
    const float* adj_base = adj + (size_t)(i_base + arow) * N + j0 + aseg * 4;
    const __half* wh_base = g_Wh_h + (size_t)(j0 + arow) * 64 + aseg * 8;

#define PREFETCH(tt)                                                           \
    do {                                                                       \
        const uint32_t st_ = sb + ((tt) % 3) * STAGE_B;                        \
        const float* as_ = adj_base + (tt) * TJ;                               \
        _Pragma("unroll")                                                      \
        for (int q_ = 0; q_ < 8; q_++)                                         \
            CP_ASYNC16(st_ + (q_ * 16 + arow) * (ADJ_STR * 4) + aseg * 16,     \
                       as_ + (size_t)(q_ * 16) * N);                           \
        const uint32_t wst_ = st_ + STAGE_ADJ_B;                               \
        const __half* ws_ = wh_base + (size_t)((tt) * TJ) * 64;                \
        CP_ASYNC16(wst_ + arow * 144 + aseg * 16, ws_);                        \
        CP_ASYNC16(wst_ + (16 + arow) * 144 + aseg * 16, ws_ + 16 * 64);       \
        CP_COMMIT();                                                           \
    } while (0)

    // e1 fp16 splats (invariant)
    __half2 e1x2[2][2], e1y2[2][2];
    #pragma unroll
    for (int mt = 0; mt < 2; mt++)
        #pragma unroll
        for (int aa = 0; aa < 2; aa++) {
            float2 e1f = g_E1P[i_warp + mt * 16 + aa * 8 + r0];
            e1x2[mt][aa] = __half2half2(__float2half(e1f.x));
            e1y2[mt][aa] = __half2half2(__float2half(e1f.y));
        }

    float acc[2][8][4];
    float accden[2][4];
    #pragma unroll
    for (int mt = 0; mt < 2; mt++) {
        #pragma unroll
        for (int nt = 0; nt < 8; nt++)
            #pragma unroll
            for (int e = 0; e < 4; e++) acc[mt][nt][e] = 0.f;
        #pragma unroll
        for (int e = 0; e < 4; e++) accden[mt][e] = 0.f;
    }
    const uint32_t bones = (r0 == 0) ? 0x3C003C00u : 0u;   // fp16 ones column

    // ldmatrix lane map (x4.trans)
    const int mm = lane >> 3;
    const int ldsm_row = (mm & 1) * 8 + (lane & 7);
    const int ldsm_f   = mm >> 1;

    PREFETCH(0); PREFETCH(1); PREFETCH(2);

    #pragma unroll 1
    for (int it = 0; it < NT; it++) {
        const int s = it % 3;
        const int jt = j0 + it * TJ;
        CP_WAIT2();
        __syncthreads();

        // ---- e2 fp16 pair loads (L1-hot) ----
        __half2 ex2[2][2], ey2[2][2];
        #pragma unroll
        for (int kt = 0; kt < 2; kt++)
            #pragma unroll
            for (int hh = 0; hh < 2; hh++) {
                const int jj = jt + kt * 16 + hh * 8 + c0;
                ex2[kt][hh] = *(const __half2*)&g_E2XH[jj];
                ey2[kt][hh] = *(const __half2*)&g_E2YH[jj];
            }

        // ---- A fragments (P) from smem adj (conflict-free float2 LDS) ----
        const float* adjS = (const float*)(smem + s * STAGE_B);
        uint32_t afr[2][2][4];
        #pragma unroll
        for (int mt = 0; mt < 2; mt++)
            #pragma unroll
            for (int kt = 0; kt < 2; kt++)
                #pragma unroll
                for (int aa = 0; aa < 2; aa++)
                    #pragma unroll
                    for (int hh = 0; hh < 2; hh++) {
                        const int R = warp * 32 + mt * 16 + aa * 8 + r0;
                        float2 ad = *(const float2*)&adjS[R * ADJ_STR +
                                                          kt * 16 + hh * 8 + c0];
                        __half2 ah = __floats2half2_rn(ad.x, ad.y);
                        __half2 u  = __hmul2(e1x2[mt][aa], ex2[kt][hh]);
                        __half2 v  = __hmul2(e1y2[mt][aa], ey2[kt][hh]);
                        __half2 p  = __hmul2(__hmax2(u, v), ah);
                        afr[mt][kt][aa + 2 * hh] = *(uint32_t*)&p;
                    }

        // ---- B fragments to regs (LDSM from Wh stage s) ----
        uint32_t bq[2][4][4];
        #pragma unroll
        for (int kt = 0; kt < 2; kt++) {
            const uint32_t abase = sb + s * STAGE_B + STAGE_ADJ_B
                                   + (kt * 16 + ldsm_row) * 144 + ldsm_f * 16;
            #pragma unroll
            for (int p = 0; p < 4; p++)
                LDSM_X4_T(bq[kt][p][0], bq[kt][p][1], bq[kt][p][2], bq[kt][p][3],
                          abase + p * 32);
        }
        __syncthreads();   // all warps done with stage s

        // ---- prefetch tile it+3 into stage s ----
        if (it + 3 < NT) { PREFETCH(it + 3); } else { CP_COMMIT(); }

        // ---- MMAs (all operands in registers) ----
        #pragma unroll
        for (int kt = 0; kt < 2; kt++) {
            #pragma unroll
            for (int p = 0; p < 4; p++) {
                MMA_F16(acc[0][2 * p],     afr[0][kt], bq[kt][p][0], bq[kt][p][1]);
                MMA_F16(acc[0][2 * p + 1], afr[0][kt], bq[kt][p][2], bq[kt][p][3]);
                MMA_F16(acc[1][2 * p],     afr[1][kt], bq[kt][p][0], bq[kt][p][1]);
                MMA_F16(acc[1][2 * p + 1], afr[1][kt], bq[kt][p][2], bq[kt][p][3]);
            }
            MMA_F16(accden[0], afr[0][kt], bones, bones);
            MMA_F16(accden[1], afr[1][kt], bones, bones);
        }
    }

    // ---- epilogue ----
    float* ob = g_acc[js];
    #pragma unroll
    for (int mt = 0; mt < 2; mt++) {
        const int ir = i_warp + mt * 16 + r0;
        #pragma unroll
        for (int nt = 0; nt < 8; nt++) {
            const int fc = nt * 8 + c0;
            *(float2*)&ob[(size_t)ir * FOUT + fc] =
                make_float2(acc[mt][nt][0], acc[mt][nt][1]);
            *(float2*)&ob[(size_t)(ir + 8) * FOUT + fc] =
                make_float2(acc[mt][nt][2], acc[mt][nt][3]);
        }
    }
    if ((lane & 3) == 0) {
        #pragma unroll
        for (int mt = 0; mt < 2; mt++) {
            g_den[js][i_warp + mt * 16 + r0]     = accden[mt][0];
            g_den[js][i_warp + mt * 16 + 8 + r0] = accden[mt][2];
        }
    }
}

// ============================================================
// Kernel C: combine partials, normalize, ELU.
// ============================================================
__global__ void __launch_bounds__(256) gat_final(float* __restrict__ out)
{
    const int idx = blockIdx.x * 256 + threadIdx.x;   // < N*FOUT
    const int i = idx >> 6;
    float d = 0.f, v = 0.f;
    #pragma unroll
    for (int s = 0; s < JSPLIT; s++) {
        d += g_den[s][i];
        v += g_acc[s][idx];
    }
    float h = v / d;
    out[idx] = (h > 0.f) ? h : expm1f(h);
}

// ============================================================
extern "C" void kernel_launch(void* const* d_in, const int* in_sizes, int n_in,
                              void* d_out, int out_size)
{
    const float* x   = (const float*)d_in[0];
    const float* adj = (const float*)d_in[1];
    const float* W   = (const float*)d_in[2];
    const float* a   = (const float*)d_in[3];
    float* out = (float*)d_out;

    cudaFuncSetAttribute(gat_prep, cudaFuncAttributeMaxDynamicSharedMemorySize,
                         PREP_SMEM);
    cudaFuncSetAttribute(gat_attn, cudaFuncAttributeMaxDynamicSharedMemorySize,
                         SMEMB_BYTES);

    gat_prep<<<N / 32, 256, PREP_SMEM>>>(x, W, a);
    gat_attn<<<dim3(N / TI, JSPLIT), TI, SMEMB_BYTES>>>(adj);
    gat_final<<<(N * FOUT) / 256, 256>>>(out);
}

// round 13
// speedup vs baseline: 1.2067x; 1.0926x over previous
#include <cuda_runtime.h>
#include <cuda_fp16.h>
#include <cstdint>

// GAT layer, N=8192, Fin=128, Fout=64.
// inputs: x [N,128] f32, adj [N,N] f32 (0/1), W [128,64] f32, a [128,1] f32
// output: [N,64] f32

#define N      8192
#define FOUT   64
#define TI     128
#define TJ     32
#define JSPLIT 16
#define JRANGE (N / JSPLIT)     // 512
#define NT     (JRANGE / TJ)    // 16

#define ADJ_STR 40                        // floats per adj smem row (160 B, conflict-free)
#define WH_STR  72                        // halves per Wh smem row (144 B)
#define STAGE_ADJ_B (TI * ADJ_STR * 4)    // 20480
#define STAGE_WH_B  (TJ * WH_STR * 2)     // 4608
#define STAGE_B     (STAGE_ADJ_B + STAGE_WH_B)   // 25088
#define NSTAGE 3
#define SMEMB_BYTES (NSTAGE * STAGE_B)    // 75264

// ---------------- device scratch ----------------
__device__ float2 g_E1P[N];                  // (e^Wh1, e^{0.2 Wh1}) fp32
__device__ __half g_E2XH[N];                 // fp16 e^Wh2
__device__ __half g_E2YH[N];                 // fp16 e^{0.2 Wh2}
__device__ __half g_Wh_h[N * FOUT];          // Wh [j][f] fp16
__device__ float  g_acc[JSPLIT][N * FOUT];   // partial numerators [js][i][f]
__device__ float  g_den[JSPLIT][N];          // partial denominators

// ---------------- helpers ----------------
#define CP_ASYNC16(dst, src) \
    asm volatile("cp.async.cg.shared.global [%0], [%1], 16;" :: "r"(dst), "l"(src))
#define CP_COMMIT() asm volatile("cp.async.commit_group;")
#define CP_WAIT2()  asm volatile("cp.async.wait_group 2;" ::: "memory")

#define LDSM_X4(d0, d1, d2, d3, addr)                                          \
    asm volatile("ldmatrix.sync.aligned.m8n8.x4.shared.b16 "                   \
                 "{%0,%1,%2,%3}, [%4];"                                        \
                 : "=r"(d0), "=r"(d1), "=r"(d2), "=r"(d3) : "r"(addr))

#define LDSM_X4_T(d0, d1, d2, d3, addr)                                        \
    asm volatile("ldmatrix.sync.aligned.m8n8.x4.trans.shared.b16 "             \
                 "{%0,%1,%2,%3}, [%4];"                                        \
                 : "=r"(d0), "=r"(d1), "=r"(d2), "=r"(d3) : "r"(addr))

#define MMA_F16(D, A, B0, B1)                                                 \
    asm("mma.sync.aligned.m16n8k16.row.col.f32.f16.f16.f32 "                  \
        "{%0,%1,%2,%3},{%4,%5,%6,%7},{%8,%9},{%0,%1,%2,%3};"                  \
        : "+f"((D)[0]), "+f"((D)[1]), "+f"((D)[2]), "+f"((D)[3])              \
        : "r"((A)[0]), "r"((A)[1]), "r"((A)[2]), "r"((A)[3]),                 \
          "r"(B0), "r"(B1))

#define MMA_F16R(D, A0, A1, A2, A3, B0, B1)                                   \
    asm("mma.sync.aligned.m16n8k16.row.col.f32.f16.f16.f32 "                  \
        "{%0,%1,%2,%3},{%4,%5,%6,%7},{%8,%9},{%0,%1,%2,%3};"                  \
        : "+f"((D)[0]), "+f"((D)[1]), "+f"((D)[2]), "+f"((D)[3])              \
        : "r"(A0), "r"(A1), "r"(A2), "r"(A3), "r"(B0), "r"(B1))

// ============================================================
// Kernel A: Wh = x@W via fp16 MMA; dots + exp tables from f32 C-frags.
// grid 128 x 128 threads (4 warps); 64 rows/block, warp w -> rows 16w..16w+15.
// smem: xh [64][136 halves] (272B rows) | wh [128][72 halves] (144B rows) | aS f32[128]
// ============================================================
#define P_XH 0
#define P_WH 17408
#define P_A  (17408 + 18432)
#define PREP_SMEM (P_A + 512)   // 36352

__global__ void __launch_bounds__(128) gat_prep(const float* __restrict__ x,
                                                const float* __restrict__ W,
                                                const float* __restrict__ a)
{
    extern __shared__ char psm[];
    __half* xh = (__half*)(psm + P_XH);     // stride 136 halves
    __half* wh = (__half*)(psm + P_WH);     // stride 72 halves
    float*  aS = (float*)(psm + P_A);

    const int t = threadIdx.x;
    const int row0 = blockIdx.x * 64;

    // stage x tile (64x128 f32 -> fp16)
    const float* xb = x + (size_t)row0 * 128;
    #pragma unroll
    for (int q = 0; q < 16; q++) {
        const int flat = (q * 128 + t) * 4;
        const int r = flat >> 7, c = flat & 127;
        float4 v = *(const float4*)&xb[flat];
        __half2 h0 = __floats2half2_rn(v.x, v.y);
        __half2 h1 = __floats2half2_rn(v.z, v.w);
        uint2 u = make_uint2(*(uint32_t*)&h0, *(uint32_t*)&h1);
        *(uint2*)&xh[r * 136 + c] = u;
    }
    // stage W (128x64 f32 -> fp16, [k][f])
    #pragma unroll
    for (int q = 0; q < 16; q++) {
        const int flat = (q * 128 + t) * 4;
        const int k = flat >> 6, f = flat & 63;
        float4 v = *(const float4*)&W[flat];
        __half2 h0 = __floats2half2_rn(v.x, v.y);
        __half2 h1 = __floats2half2_rn(v.z, v.w);
        uint2 u = make_uint2(*(uint32_t*)&h0, *(uint32_t*)&h1);
        *(uint2*)&wh[k * 72 + f] = u;
    }
    if (t < 32) *(float4*)&aS[t * 4] = *(const float4*)&a[t * 4];
    __syncthreads();

    const int lane = t & 31, warp = t >> 5;
    const int rbase = warp * 16;
    const int mm = lane >> 3;
    const uint32_t sb = (uint32_t)__cvta_generic_to_shared(psm);

    // A ldmatrix (non-trans): matrix mm -> rows (mm&1)*8+(lane&7), k-off (mm>>1)*8
    const uint32_t A_base = sb + P_XH +
        ((rbase + (mm & 1) * 8 + (lane & 7)) * 136 + (mm >> 1) * 8) * 2;
    // B ldmatrix.trans: same mapping as attn kernel (proven)
    const int ldsm_row = (mm & 1) * 8 + (lane & 7);
    const int ldsm_f   = mm >> 1;
    const uint32_t B_base = sb + P_WH + ldsm_row * 144 + ldsm_f * 16;

    float c[8][4];
    #pragma unroll
    for (int nt = 0; nt < 8; nt++)
        #pragma unroll
        for (int e = 0; e < 4; e++) c[nt][e] = 0.f;

    #pragma unroll
    for (int kc = 0; kc < 8; kc++) {
        uint32_t A0, A1, A2, A3;
        LDSM_X4(A0, A1, A2, A3, A_base + kc * 32);
        #pragma unroll
        for (int p = 0; p < 4; p++) {
            uint32_t q0, q1, q2, q3;
            LDSM_X4_T(q0, q1, q2, q3, B_base + kc * 16 * 144 + p * 32);
            MMA_F16R(c[2 * p],     A0, A1, A2, A3, q0, q1);
            MMA_F16R(c[2 * p + 1], A0, A1, A2, A3, q2, q3);
        }
    }

    // epilogue: dots + Wh fp16 store
    const int qq = lane & 3, r0 = lane >> 2;
    const int rowlo = row0 + rbase + r0;
    float p1lo = 0.f, p1hi = 0.f, p2lo = 0.f, p2hi = 0.f;
    #pragma unroll
    for (int nt = 0; nt < 8; nt++) {
        const int col = nt * 8 + 2 * qq;
        const float a1l = aS[col], a1h = aS[col + 1];
        const float a2l = aS[64 + col], a2h = aS[64 + col + 1];
        p1lo += c[nt][0] * a1l + c[nt][1] * a1h;
        p1hi += c[nt][2] * a1l + c[nt][3] * a1h;
        p2lo += c[nt][0] * a2l + c[nt][1] * a2h;
        p2hi += c[nt][2] * a2l + c[nt][3] * a2h;
        __half2 h0 = __floats2half2_rn(c[nt][0], c[nt][1]);
        __half2 h1 = __floats2half2_rn(c[nt][2], c[nt][3]);
        *(uint32_t*)&g_Wh_h[(size_t)rowlo * 64 + col]       = *(uint32_t*)&h0;
        *(uint32_t*)&g_Wh_h[(size_t)(rowlo + 8) * 64 + col] = *(uint32_t*)&h1;
    }
    p1lo += __shfl_xor_sync(0xffffffffu, p1lo, 1);
    p1lo += __shfl_xor_sync(0xffffffffu, p1lo, 2);
    p1hi += __shfl_xor_sync(0xffffffffu, p1hi, 1);
    p1hi += __shfl_xor_sync(0xffffffffu, p1hi, 2);
    p2lo += __shfl_xor_sync(0xffffffffu, p2lo, 1);
    p2lo += __shfl_xor_sync(0xffffffffu, p2lo, 2);
    p2hi += __shfl_xor_sync(0xffffffffu, p2hi, 1);
    p2hi += __shfl_xor_sync(0xffffffffu, p2hi, 2);

    if (qq == 0) {
        g_E1P[rowlo]      = make_float2(__expf(p1lo), __expf(0.2f * p1lo));
        g_E1P[rowlo + 8]  = make_float2(__expf(p1hi), __expf(0.2f * p1hi));
        g_E2XH[rowlo]     = __float2half(__expf(p2lo));
        g_E2YH[rowlo]     = __float2half(__expf(0.2f * p2lo));
        g_E2XH[rowlo + 8] = __float2half(__expf(p2hi));
        g_E2YH[rowlo + 8] = __float2half(__expf(0.2f * p2hi));
    }
}

// ============================================================
// Kernel B: 3-stage cp.async ring (adj+Wh) + fp16 MMA (den via ones column).
// grid (64, 16) x 128 threads (4 warps), 3 blocks/SM. 34 MMAs/warp/tile.
// (byte-identical to the 92.6us R9 version)
// ============================================================
__global__ void __launch_bounds__(128, 3) gat_attn(const float* __restrict__ adj)
{
    extern __shared__ char smem[];
    const int t = threadIdx.x, lane = t & 31, warp = t >> 5;
    const int ib = blockIdx.x, js = blockIdx.y;
    const int i_base = ib * TI, i_warp = i_base + warp * 32;
    const int j0 = js * JRANGE;
    const int r0 = lane >> 2, c0 = (lane & 3) * 2;

    const uint32_t sb = (uint32_t)__cvta_generic_to_shared(smem);

    // staging maps (fully coalesced 128B chunks)
    const int arow = t >> 3, aseg = t & 7;
    const float* adj_base = adj + (size_t)(i_base + arow) * N + j0 + aseg * 4;
    const __half* wh_base = g_Wh_h + (size_t)(j0 + arow) * 64 + aseg * 8;

#define PREFETCH(tt)                                                           \
    do {                                                                       \
        const uint32_t st_ = sb + ((tt) % 3) * STAGE_B;                        \
        const float* as_ = adj_base + (tt) * TJ;                               \
        _Pragma("unroll")                                                      \
        for (int q_ = 0; q_ < 8; q_++)                                         \
            CP_ASYNC16(st_ + (q_ * 16 + arow) * (ADJ_STR * 4) + aseg * 16,     \
                       as_ + (size_t)(q_ * 16) * N);                           \
        const uint32_t wst_ = st_ + STAGE_ADJ_B;                               \
        const __half* ws_ = wh_base + (size_t)((tt) * TJ) * 64;                \
        CP_ASYNC16(wst_ + arow * 144 + aseg * 16, ws_);                        \
        CP_ASYNC16(wst_ + (16 + arow) * 144 + aseg * 16, ws_ + 16 * 64);       \
        CP_COMMIT();                                                           \
    } while (0)

    // e1 fp16 splats (invariant)
    __half2 e1x2[2][2], e1y2[2][2];
    #pragma unroll
    for (int mt = 0; mt < 2; mt++)
        #pragma unroll
        for (int aa = 0; aa < 2; aa++) {
            float2 e1f = g_E1P[i_warp + mt * 16 + aa * 8 + r0];
            e1x2[mt][aa] = __half2half2(__float2half(e1f.x));
            e1y2[mt][aa] = __half2half2(__float2half(e1f.y));
        }

    float acc[2][8][4];
    float accden[2][4];
    #pragma unroll
    for (int mt = 0; mt < 2; mt++) {
        #pragma unroll
        for (int nt = 0; nt < 8; nt++)
            #pragma unroll
            for (int e = 0; e < 4; e++) acc[mt][nt][e] = 0.f;
        #pragma unroll
        for (int e = 0; e < 4; e++) accden[mt][e] = 0.f;
    }
    const uint32_t bones = (r0 == 0) ? 0x3C003C00u : 0u;   // fp16 ones column

    // ldmatrix lane map (x4.trans)
    const int mm = lane >> 3;
    const int ldsm_row = (mm & 1) * 8 + (lane & 7);
    const int ldsm_f   = mm >> 1;

    PREFETCH(0); PREFETCH(1); PREFETCH(2);

    #pragma unroll 1
    for (int it = 0; it < NT; it++) {
        const int s = it % 3;
        const int jt = j0 + it * TJ;
        CP_WAIT2();
        __syncthreads();

        // ---- e2 fp16 pair loads (L1-hot) ----
        __half2 ex2[2][2], ey2[2][2];
        #pragma unroll
        for (int kt = 0; kt < 2; kt++)
            #pragma unroll
            for (int hh = 0; hh < 2; hh++) {
                const int jj = jt + kt * 16 + hh * 8 + c0;
                ex2[kt][hh] = *(const __half2*)&g_E2XH[jj];
                ey2[kt][hh] = *(const __half2*)&g_E2YH[jj];
            }

        // ---- A fragments (P) from smem adj (conflict-free float2 LDS) ----
        const float* adjS = (const float*)(smem + s * STAGE_B);
        uint32_t afr[2][2][4];
        #pragma unroll
        for (int mt = 0; mt < 2; mt++)
            #pragma unroll
            for (int kt = 0; kt < 2; kt++)
                #pragma unroll
                for (int aa = 0; aa < 2; aa++)
                    #pragma unroll
                    for (int hh = 0; hh < 2; hh++) {
                        const int R = warp * 32 + mt * 16 + aa * 8 + r0;
                        float2 ad = *(const float2*)&adjS[R * ADJ_STR +
                                                          kt * 16 + hh * 8 + c0];
                        __half2 ah = __floats2half2_rn(ad.x, ad.y);
                        __half2 u  = __hmul2(e1x2[mt][aa], ex2[kt][hh]);
                        __half2 v  = __hmul2(e1y2[mt][aa], ey2[kt][hh]);
                        __half2 p  = __hmul2(__hmax2(u, v), ah);
                        afr[mt][kt][aa + 2 * hh] = *(uint32_t*)&p;
                    }

        // ---- B fragments to regs (LDSM from Wh stage s) ----
        uint32_t bq[2][4][4];
        #pragma unroll
        for (int kt = 0; kt < 2; kt++) {
            const uint32_t abase = sb + s * STAGE_B + STAGE_ADJ_B
                                   + (kt * 16 + ldsm_row) * 144 + ldsm_f * 16;
            #pragma unroll
            for (int p = 0; p < 4; p++)
                LDSM_X4_T(bq[kt][p][0], bq[kt][p][1], bq[kt][p][2], bq[kt][p][3],
                          abase + p * 32);
        }
        __syncthreads();   // all warps done with stage s

        // ---- prefetch tile it+3 into stage s ----
        if (it + 3 < NT) { PREFETCH(it + 3); } else { CP_COMMIT(); }

        // ---- MMAs (all operands in registers) ----
        #pragma unroll
        for (int kt = 0; kt < 2; kt++) {
            #pragma unroll
            for (int p = 0; p < 4; p++) {
                MMA_F16(acc[0][2 * p],     afr[0][kt], bq[kt][p][0], bq[kt][p][1]);
                MMA_F16(acc[0][2 * p + 1], afr[0][kt], bq[kt][p][2], bq[kt][p][3]);
                MMA_F16(acc[1][2 * p],     afr[1][kt], bq[kt][p][0], bq[kt][p][1]);
                MMA_F16(acc[1][2 * p + 1], afr[1][kt], bq[kt][p][2], bq[kt][p][3]);
            }
            MMA_F16(accden[0], afr[0][kt], bones, bones);
            MMA_F16(accden[1], afr[1][kt], bones, bones);
        }
    }

    // ---- epilogue ----
    float* ob = g_acc[js];
    #pragma unroll
    for (int mt = 0; mt < 2; mt++) {
        const int ir = i_warp + mt * 16 + r0;
        #pragma unroll
        for (int nt = 0; nt < 8; nt++) {
            const int fc = nt * 8 + c0;
            *(float2*)&ob[(size_t)ir * FOUT + fc] =
                make_float2(acc[mt][nt][0], acc[mt][nt][1]);
            *(float2*)&ob[(size_t)(ir + 8) * FOUT + fc] =
                make_float2(acc[mt][nt][2], acc[mt][nt][3]);
        }
    }
    if ((lane & 3) == 0) {
        #pragma unroll
        for (int mt = 0; mt < 2; mt++) {
            g_den[js][i_warp + mt * 16 + r0]     = accden[mt][0];
            g_den[js][i_warp + mt * 16 + 8 + r0] = accden[mt][2];
        }
    }
}

// ============================================================
// Kernel C: combine partials, normalize, ELU.
// ============================================================
__global__ void __launch_bounds__(256) gat_final(float* __restrict__ out)
{
    const int idx = blockIdx.x * 256 + threadIdx.x;   // < N*FOUT
    const int i = idx >> 6;
    float d = 0.f, v = 0.f;
    #pragma unroll
    for (int s = 0; s < JSPLIT; s++) {
        d += g_den[s][i];
        v += g_acc[s][idx];
    }
    float h = v / d;
    out[idx] = (h > 0.f) ? h : expm1f(h);
}

// ============================================================
extern "C" void kernel_launch(void* const* d_in, const int* in_sizes, int n_in,
                              void* d_out, int out_size)
{
    const float* x   = (const float*)d_in[0];
    const float* adj = (const float*)d_in[1];
    const float* W   = (const float*)d_in[2];
    const float* a   = (const float*)d_in[3];
    float* out = (float*)d_out;

    cudaFuncSetAttribute(gat_prep, cudaFuncAttributeMaxDynamicSharedMemorySize,
                         PREP_SMEM);
    cudaFuncSetAttribute(gat_attn, cudaFuncAttributeMaxDynamicSharedMemorySize,
                         SMEMB_BYTES);

    gat_prep<<<N / 64, 128, PREP_SMEM>>>(x, W, a);
    gat_attn<<<dim3(N / TI, JSPLIT), TI, SMEMB_BYTES>>>(adj);
    gat_final<<<(N * FOUT) / 256, 256>>>(out);
}